// round 13
// baseline (speedup 1.0000x reference)
#include <cuda_runtime.h>
#include <cuda_bf16.h>

// VectorQuantizer forward, single fused kernel:
//   q    = codebook[categories]   (row gather, 512x768 codebook -> L2 resident)
//   out  = q
//   loss = 1.25 * mean((q - inputs)^2)
//
// Loss reduction: one packed 64-bit integer atomicAdd per block.
//   bits [0:50)  : fixed-point (2^20) partial sum accumulator (max ~1.05e14 < 2^50)
//   bits [50:64) : block-arrival count (14 bits, max 16383 >= 4096 blocks)
// Integer adds are associative -> bit-deterministic; the atomicAdd return
// value lets the last block detect completion AND recover the full sum.
//
// Index distribution: warp-local. Lane l<16 loads cat[base+l]; per-iteration
// row index is recovered with __shfl_sync. No shared memory for indices, no
// __syncthreads anywhere -> block prologue fully overlaps with payload loads.
//
// Config notes (GB300, measured across R3-R12):
//  - TPB=256, 8 blk/SM -> 64/64 warps, regs 32. Best mainloop 60.0us.
//  - ROWS=16 (4096 blocks) ~= ROWS=8; wave tail not binding (DRAM pinned 74%).
//  - No __ldcs/__stcs (harmful). unroll 4 (8 blew regs).
//
// inputs:     [65536, 768] f32
// categories: [65536]      int32
// codebook:   [512, 768]   f32
// out:        65536*768 f32 quantized_st, then 1 f32 loss (if out_size permits)

#define VQ_BS    65536
#define VQ_D4    192                  // float4s per row
#define VQ_ROWS  16                   // rows per block
#define VQ_TPB   256                  // threads per block
#define VQ_F4PB  (VQ_ROWS * VQ_D4)    // 3072 float4s per block
#define VQ_ITERS (VQ_F4PB / VQ_TPB)   // 12 per thread
#define VQ_NBLK  (VQ_BS / VQ_ROWS)    // 4096 blocks

#define VQ_CNT_SHIFT 50
#define VQ_FX_SCALE  1048576.0        // 2^20

__device__ unsigned long long g_vq_acc = 0ULL;   // reset by last block -> replay-idempotent

__global__ __launch_bounds__(VQ_TPB, 8) void vq_kernel(
    const float4* __restrict__ in,
    const int* __restrict__ cat,
    const float4* __restrict__ cb,
    float4* __restrict__ out,
    float* __restrict__ loss_out,
    int write_loss)
{
    const int t    = threadIdx.x;                    // 0..255
    const int lane = t & 31;
    const size_t blk_f4 = (size_t)blockIdx.x * VQ_F4PB;

    // Warp-local index copy: lane l < VQ_ROWS holds cat[base+l]. No barrier.
    int my_c = 0;
    if (lane < VQ_ROWS)
        my_c = __ldg(&cat[blockIdx.x * VQ_ROWS + lane]) & 511;  // mask: no-op on valid data

    float s = 0.0f;

    #pragma unroll 4
    for (int k = 0; k < VQ_ITERS; k++) {
        const int idx = t + k * VQ_TPB;              // 0..3071 within block tile
        const int row = idx / VQ_D4;                 // const-div -> mul/shift
        const int col = idx - row * VQ_D4;
        const int c   = __shfl_sync(0xffffffffu, my_c, row);
        const size_t gib = blk_f4 + idx;             // flat, fully coalesced
        float4 a = in[gib];
        float4 q = cb[(size_t)c * VQ_D4 + col];
        out[gib] = q;
        float dx = q.x - a.x;
        float dy = q.y - a.y;
        float dz = q.z - a.z;
        float dw = q.w - a.w;
        s += dx*dx + dy*dy + dz*dz + dw*dw;
    }

    // block reduction: 8 warps of 32
    #pragma unroll
    for (int o = 16; o > 0; o >>= 1)
        s += __shfl_down_sync(0xffffffffu, s, o);

    __shared__ float ws[8];
    if ((t & 31) == 0) ws[t >> 5] = s;
    __syncthreads();

    if (t == 0) {
        float tot = ws[0] + ws[1] + ws[2] + ws[3] + ws[4] + ws[5] + ws[6] + ws[7];
        // fixed-point: ~2.4e4 per block -> ~2.5e10 scaled; total ~1.05e14 < 2^50
        unsigned long long fx = (unsigned long long)((double)tot * VQ_FX_SCALE);
        unsigned long long packed = (1ULL << VQ_CNT_SHIFT) + fx;
        unsigned long long old = atomicAdd(&g_vq_acc, packed);

        if ((old >> VQ_CNT_SHIFT) == (unsigned long long)(VQ_NBLK - 1)) {
            unsigned long long full = (old + packed) & ((1ULL << VQ_CNT_SHIFT) - 1ULL);
            if (write_loss) {
                const double inv_n = 1.0 / ((double)VQ_BS * 768.0);
                double mse = ((double)full / VQ_FX_SCALE) * inv_n;
                // loss = (CODEBOOK_COST + COMMITMENT_COST) * mse = 1.25 * mse
                loss_out[(size_t)VQ_BS * 768] = (float)(1.25 * mse);
            }
            g_vq_acc = 0ULL;   // reset for next graph replay (no other block alive)
        }
    }
}

extern "C" void kernel_launch(void* const* d_in, const int* in_sizes, int n_in,
                              void* d_out, int out_size)
{
    const float4* in  = (const float4*)d_in[0];
    const int*    cat = (const int*)d_in[1];
    const float4* cb  = (const float4*)d_in[2];
    float*        out = (float*)d_out;

    const int write_loss = (out_size > VQ_BS * 768) ? 1 : 0;
    vq_kernel<<<VQ_NBLK, VQ_TPB>>>(in, cat, cb, (float4*)out, out, write_loss);
}

// round 14
// speedup vs baseline: 1.0044x; 1.0044x over previous
#include <cuda_runtime.h>
#include <cuda_bf16.h>

// VectorQuantizer forward, single fused kernel — CONVERGED CONFIG.
//   q    = codebook[categories]   (row gather, 512x768 codebook -> L2 resident)
//   out  = q
//   loss = 1.25 * mean((q - inputs)^2)
//
// Loss reduction: one packed 64-bit integer atomicAdd per block.
//   bits [0:50)  : fixed-point (2^20) partial sum (max ~1.05e14 < 2^50)
//   bits [50:64) : block-arrival count (14 bits >= 4096 blocks)
// Integer adds are associative -> bit-deterministic; the atomicAdd return
// value lets the last block detect completion AND recover the full sum
// (no fence, no second pass, no second kernel).
//
// Index distribution: warp-local. Lane l<16 holds cat[base+l]; per-iteration
// row index recovered via __shfl_sync. No smem for indices, no __syncthreads
// before the payload loop.
//
// Convergence evidence (GB300, R3-R13):
//  - DRAM pinned 73-75% (5.85-5.94 TB/s) across TPB {192,256}, ROWS {8,16,32},
//    unroll {3,4,8}, cache hints on/off, smem vs shuffle index. This is the
//    practical HBM3e ceiling for a 1:1 interleaved read:write stream; the
//    384MB payload is irreducible.
//  - TPB=256 @ 8 blk/SM = 64/64 warps, 32 regs (RF exactly full). Best.
//  - __ldcs/__stcs harmful (~2.7us). __threadfence tail harmful (~3-5us).
//  - kernel best 59.7us; total-kernel = 5.3-6.6us harness noise band.
//
// inputs:     [65536, 768] f32
// categories: [65536]      int32
// codebook:   [512, 768]   f32
// out:        65536*768 f32 quantized_st, then 1 f32 loss (if out_size permits)

#define VQ_BS    65536
#define VQ_D4    192                  // float4s per row
#define VQ_ROWS  16                   // rows per block
#define VQ_TPB   256                  // threads per block
#define VQ_F4PB  (VQ_ROWS * VQ_D4)    // 3072 float4s per block
#define VQ_ITERS (VQ_F4PB / VQ_TPB)   // 12 per thread
#define VQ_NBLK  (VQ_BS / VQ_ROWS)    // 4096 blocks

#define VQ_CNT_SHIFT 50
#define VQ_FX_SCALE  1048576.0        // 2^20

__device__ unsigned long long g_vq_acc = 0ULL;   // reset by last block -> replay-idempotent

__global__ __launch_bounds__(VQ_TPB, 8) void vq_kernel(
    const float4* __restrict__ in,
    const int* __restrict__ cat,
    const float4* __restrict__ cb,
    float4* __restrict__ out,
    float* __restrict__ loss_out,
    int write_loss)
{
    const int t    = threadIdx.x;                    // 0..255
    const int lane = t & 31;
    const size_t blk_f4 = (size_t)blockIdx.x * VQ_F4PB;

    // Warp-local index copy: lane l < VQ_ROWS holds cat[base+l]. No barrier.
    int my_c = 0;
    if (lane < VQ_ROWS)
        my_c = __ldg(&cat[blockIdx.x * VQ_ROWS + lane]) & 511;  // mask: no-op on valid data

    float s = 0.0f;

    #pragma unroll 4
    for (int k = 0; k < VQ_ITERS; k++) {
        const int idx = t + k * VQ_TPB;              // 0..3071 within block tile
        const int row = idx / VQ_D4;                 // const-div -> mul/shift
        const int col = idx - row * VQ_D4;
        const int c   = __shfl_sync(0xffffffffu, my_c, row);
        const size_t gib = blk_f4 + idx;             // flat, fully coalesced
        float4 a = in[gib];
        float4 q = cb[(size_t)c * VQ_D4 + col];
        out[gib] = q;
        float dx = q.x - a.x;
        float dy = q.y - a.y;
        float dz = q.z - a.z;
        float dw = q.w - a.w;
        s += dx*dx + dy*dy + dz*dz + dw*dw;
    }

    // block reduction: 8 warps of 32
    #pragma unroll
    for (int o = 16; o > 0; o >>= 1)
        s += __shfl_down_sync(0xffffffffu, s, o);

    __shared__ float ws[8];
    if ((t & 31) == 0) ws[t >> 5] = s;
    __syncthreads();

    if (t == 0) {
        float tot = ws[0] + ws[1] + ws[2] + ws[3] + ws[4] + ws[5] + ws[6] + ws[7];
        // fixed-point: ~2.4e4 per block -> ~2.5e10 scaled; total ~1.05e14 < 2^50
        unsigned long long fx = (unsigned long long)((double)tot * VQ_FX_SCALE);
        unsigned long long packed = (1ULL << VQ_CNT_SHIFT) + fx;
        unsigned long long old = atomicAdd(&g_vq_acc, packed);

        if ((old >> VQ_CNT_SHIFT) == (unsigned long long)(VQ_NBLK - 1)) {
            unsigned long long full = (old + packed) & ((1ULL << VQ_CNT_SHIFT) - 1ULL);
            if (write_loss) {
                const double inv_n = 1.0 / ((double)VQ_BS * 768.0);
                double mse = ((double)full / VQ_FX_SCALE) * inv_n;
                // loss = (CODEBOOK_COST + COMMITMENT_COST) * mse = 1.25 * mse
                loss_out[(size_t)VQ_BS * 768] = (float)(1.25 * mse);
            }
            g_vq_acc = 0ULL;   // reset for next graph replay (no other block alive)
        }
    }
}

extern "C" void kernel_launch(void* const* d_in, const int* in_sizes, int n_in,
                              void* d_out, int out_size)
{
    const float4* in  = (const float4*)d_in[0];
    const int*    cat = (const int*)d_in[1];
    const float4* cb  = (const float4*)d_in[2];
    float*        out = (float*)d_out;

    const int write_loss = (out_size > VQ_BS * 768) ? 1 : 0;
    vq_kernel<<<VQ_NBLK, VQ_TPB>>>(in, cat, cb, (float4*)out, out, write_loss);
}